// round 3
// baseline (speedup 1.0000x reference)
#include <cuda_runtime.h>
#include <cstdint>

// PowerSpectrum: values[S,N,L,M,Q] f32 -> out[S,N,L*Q*Q] f32
// out[s,n,l,q,p] = rsqrt(2l+1) * sum_{m<2l+1} v[s,n,l,m,q]*v[s,n,l,m,p]
//
// Shapes (fixed by problem): S=4, N=2000, L=4, M=7, Q=64.
// One CTA per (s,n,l) tile: load v[7][64] to smem, each of 256 threads
// computes a 1x16 strip of the 64x64 Gram matrix, streaming-stores it.
// Purely write-BW bound (~524 MB out): design minimizes everything else.

#define L_DIM 4
#define M_DIM 7
#define Q_DIM 64
#define TILE_IN   (M_DIM * Q_DIM)   // 448 floats
#define TILE_OUT  (Q_DIM * Q_DIM)   // 4096 floats

__global__ __launch_bounds__(256, 8)
void powerspectrum_kernel(const float* __restrict__ values,
                          float* __restrict__ out)
{
    const int tile = blockIdx.x;           // tile = (s*N + n)*L + l
    const int l    = tile & (L_DIM - 1);   // L = 4

    const float* vt = values + (size_t)tile * TILE_IN;
    float*       ot = out    + (size_t)tile * TILE_OUT;

    __shared__ float sv[M_DIM][Q_DIM];     // 1792 B

    const int tid = threadIdx.x;

    // Coalesced load of the 448-float tile (2 loads/thread, last partial)
    #pragma unroll
    for (int i = tid; i < TILE_IN; i += 256) {
        sv[i >> 6][i & 63] = vt[i];
    }
    __syncthreads();

    const int q  = tid >> 2;               // 0..63
    const int p0 = (tid & 3) << 4;         // 0,16,32,48

    const int   mm = 2 * l + 1;            // valid m channels
    const float cg = rsqrtf(2.0f * (float)l + 1.0f);

    float4 acc0 = make_float4(0.f, 0.f, 0.f, 0.f);
    float4 acc1 = make_float4(0.f, 0.f, 0.f, 0.f);
    float4 acc2 = make_float4(0.f, 0.f, 0.f, 0.f);
    float4 acc3 = make_float4(0.f, 0.f, 0.f, 0.f);

    // Fully unrolled, branch-free m-loop: invalid m channels contribute 0
    // (am masked to zero), matching the reference's zero-padded layout.
    // sv reads are broadcast-group conflict-free.
    #pragma unroll
    for (int m = 0; m < M_DIM; m++) {
        const float  am = (m < mm) ? sv[m][q] : 0.0f;
        const float4* row = (const float4*)&sv[m][p0];
        float4 b0 = row[0];
        float4 b1 = row[1];
        float4 b2 = row[2];
        float4 b3 = row[3];
        acc0.x += am * b0.x; acc0.y += am * b0.y; acc0.z += am * b0.z; acc0.w += am * b0.w;
        acc1.x += am * b1.x; acc1.y += am * b1.y; acc1.z += am * b1.z; acc1.w += am * b1.w;
        acc2.x += am * b2.x; acc2.y += am * b2.y; acc2.z += am * b2.z; acc2.w += am * b2.w;
        acc3.x += am * b3.x; acc3.y += am * b3.y; acc3.z += am * b3.z; acc3.w += am * b3.w;
    }

    acc0.x *= cg; acc0.y *= cg; acc0.z *= cg; acc0.w *= cg;
    acc1.x *= cg; acc1.y *= cg; acc1.z *= cg; acc1.w *= cg;
    acc2.x *= cg; acc2.y *= cg; acc2.z *= cg; acc2.w *= cg;
    acc3.x *= cg; acc3.y *= cg; acc3.z *= cg; acc3.w *= cg;

    // Streaming 128-bit stores: output is write-once; .cs keeps the 524 MB
    // stream from thrashing L2. Fully coalesced: 4 consecutive threads
    // cover one 256B q-row segment.
    float4* orow = (float4*)(ot + q * Q_DIM + p0);
    __stcs(&orow[0], acc0);
    __stcs(&orow[1], acc1);
    __stcs(&orow[2], acc2);
    __stcs(&orow[3], acc3);
}

extern "C" void kernel_launch(void* const* d_in, const int* in_sizes, int n_in,
                              void* d_out, int out_size)
{
    const float* values = (const float*)d_in[0];
    float* out = (float*)d_out;

    // tiles = S*N*L ; each tile has M*Q = 448 input floats
    const int tiles = in_sizes[0] / TILE_IN;

    powerspectrum_kernel<<<tiles, 256>>>(values, out);
}

// round 4
// speedup vs baseline: 2.9512x; 2.9512x over previous
#include <cuda_runtime.h>
#include <cstdint>

// PowerSpectrum: values[S,N,L,M,Q] f32 -> out[S,N,L*Q*Q] f32
// out[s,n,l,q,p] = rsqrt(2l+1) * sum_{m<2l+1} v[m,q]*v[m,p]
// Shapes: S=4, N=2000, L=4, M=7, Q=64 -> 32000 tiles of 64x64 outputs.
//
// R3 showed L1tex-bound (97.8%) from SMEM traffic: 1x16 strips cost
// 4.25 B of LDS per FFMA. R4: 8x4 register tile -> 1.5 B/FFMA, and
// compile-time m-count per l (skip invalid m rows entirely).

#define L_DIM 4
#define M_DIM 7
#define Q_DIM 64
#define TILE_IN   (M_DIM * Q_DIM)   // 448 floats
#define TILE_OUT  (Q_DIM * Q_DIM)   // 4096 floats

template<int MM>
__device__ __forceinline__ void gram_tile(const float (*__restrict__ sv)[Q_DIM],
                                          float* __restrict__ ot, int tid)
{
    const int pt = tid & 15;        // 0..15 -> p0 = 4*pt
    const int qt = tid >> 4;        // 0..7  -> q0 = 8*qt
    const int p0 = pt << 2;
    const int q0 = qt << 3;

    const float cg = rsqrtf((float)MM);

    float4 acc[8];
    #pragma unroll
    for (int r = 0; r < 8; r++) acc[r] = make_float4(0.f, 0.f, 0.f, 0.f);

    #pragma unroll
    for (int m = 0; m < MM; m++) {
        const float4 b  = *(const float4*)&sv[m][p0];
        const float4 a0 = *(const float4*)&sv[m][q0];
        const float4 a1 = *(const float4*)&sv[m][q0 + 4];
        const float ar[8] = {a0.x, a0.y, a0.z, a0.w, a1.x, a1.y, a1.z, a1.w};
        #pragma unroll
        for (int r = 0; r < 8; r++) {
            acc[r].x += ar[r] * b.x;
            acc[r].y += ar[r] * b.y;
            acc[r].z += ar[r] * b.z;
            acc[r].w += ar[r] * b.w;
        }
    }

    // Streaming stores: 16 threads (pt=0..15) cover one full 256B row.
    #pragma unroll
    for (int r = 0; r < 8; r++) {
        float4 o = make_float4(acc[r].x * cg, acc[r].y * cg,
                               acc[r].z * cg, acc[r].w * cg);
        __stcs((float4*)(ot + (size_t)(q0 + r) * Q_DIM + p0), o);
    }
}

__global__ __launch_bounds__(128)
void powerspectrum_kernel(const float* __restrict__ values,
                          float* __restrict__ out)
{
    const int tile = blockIdx.x;           // tile = (s*N + n)*L + l
    const int l    = tile & (L_DIM - 1);

    const float* vt = values + (size_t)tile * TILE_IN;
    float*       ot = out    + (size_t)tile * TILE_OUT;

    __shared__ float sv[M_DIM][Q_DIM];     // 1792 B

    const int tid = threadIdx.x;

    // 448 floats = 112 float4 loads; threads 0..111
    if (tid < TILE_IN / 4)
        ((float4*)&sv[0][0])[tid] = ((const float4*)vt)[tid];
    __syncthreads();

    switch (l) {
        case 0: gram_tile<1>(sv, ot, tid); break;
        case 1: gram_tile<3>(sv, ot, tid); break;
        case 2: gram_tile<5>(sv, ot, tid); break;
        default: gram_tile<7>(sv, ot, tid); break;
    }
}

extern "C" void kernel_launch(void* const* d_in, const int* in_sizes, int n_in,
                              void* d_out, int out_size)
{
    const float* values = (const float*)d_in[0];
    float* out = (float*)d_out;

    const int tiles = in_sizes[0] / TILE_IN;   // S*N*L = 32000

    powerspectrum_kernel<<<tiles, 128>>>(values, out);
}